// round 15
// baseline (speedup 1.0000x reference)
#include <cuda_runtime.h>
#include <cuda_fp16.h>
#include <cstdint>
#include <math.h>

namespace {
constexpr int B_ = 128, S_ = 128, E_ = 256, D_ = 256, O_ = 64;
constexpr int NT = 512;

// dynamic smem layout (bytes)
constexpr int OFF_EP   = 0;        // half [128][256]: x16 (prologue) then ep  65536
constexpr int OFF_XF   = 65536;    // f32 [128][64]                            32768
constexpr int OFF_YF   = 98304;    // f32 [128][64] (incl fcb)                 32768
constexpr int OFF_PWHC = 131072;   // f32 [16][2][128]                         16384
constexpr int OFF_PWHH = 147456;   // f32 [4][2][512]                          16384
constexpr int OFF_GFIN = 163840;   // f32 [2][512]                              4096
constexpr int OFF_PA   = 167936;   // f32 [256]                                 1024
constexpr int OFF_H    = 168960;   // f32 [2][256]
constexpr int OFF_C    = 171008;   // f32 [2][256]
constexpr int OFF_HCF  = 173056;   // f32 [256] own-batch hc
constexpr int OFF_SC   = 174080;   // f32 [128]
constexpr int OFF_YT   = 174592;   // f32 [2][64]
constexpr int OFF_W2   = 175104;   // f32 [256]
constexpr int OFF_FLG  = 176128;   // int flags
constexpr int SMEM_BYTES = 176192;
constexpr int FL_HC = 0, FL_YTL = 16, FL_ST = 32;   // byte offsets in FLG
}

typedef unsigned long long ull;

// fp16 weights (converted once per launch)
__device__ __half2 g_whc[D_ * E_];        // (Wh, Wc) interleaved [d][c]
__device__ __half  g_whh[D_ * 4 * D_];    // [256][1024]
__device__ __half  g_wih[O_ * 4 * D_];    // [64][1024]
__device__ float   g_hctx[B_ * (D_ + E_)];

__device__ __forceinline__ float sigm_f(float x) {
    float e = __expf(-x);
    return __fdividef(1.f, 1.f + e);
}
__device__ __forceinline__ float tanh_f(float x) {
    float e = __expf(2.f * x);
    return 1.f - __fdividef(2.f, e + 1.f);
}
__device__ __forceinline__ float tanh_a(float x) {
    float y;
    asm("tanh.approx.f32 %0, %1;" : "=f"(y) : "f"(x));
    return y;
}
__device__ __forceinline__ ull pack2(float lo, float hi) {
    ull r;
    asm("mov.b64 %0, {%1, %2};" : "=l"(r) : "f"(lo), "f"(hi));
    return r;
}
__device__ __forceinline__ ull fma2(ull a, ull b, ull c) {
    ull d;
    asm("fma.rn.f32x2 %0, %1, %2, %3;" : "=l"(d) : "l"(a), "l"(b), "l"(c));
    return d;
}
__device__ __forceinline__ float2 unpack2(ull v) {
    float2 f;
    asm("mov.b64 {%0, %1}, %2;" : "=f"(f.x), "=f"(f.y) : "l"(v));
    return f;
}
__device__ __forceinline__ ull h2_to_ull(__half2 h) {
    float2 p = __half22float2(h);
    return pack2(p.x, p.y);
}
__device__ __forceinline__ void barA() { asm volatile("bar.sync 1, 256;" ::: "memory"); }
__device__ __forceinline__ void barB() { asm volatile("bar.sync 2, 256;" ::: "memory"); }
__device__ __forceinline__ void bsync(int id) {
    asm volatile("bar.sync %0, 512;" :: "r"(id) : "memory");
}
__device__ __forceinline__ void barrive(int id) {
    asm volatile("bar.arrive %0, 512;" :: "r"(id) : "memory");
}
__device__ __forceinline__ void cluster_sync() {
    asm volatile("barrier.cluster.arrive.aligned;" ::: "memory");
    asm volatile("barrier.cluster.wait.aligned;" ::: "memory");
}
__device__ __forceinline__ unsigned int smem_u32(const void* p) {
    unsigned int a;
    asm("{ .reg .u64 t; cvta.to.shared.u64 t, %1; cvt.u32.u64 %0, t; }" : "=r"(a) : "l"(p));
    return a;
}
__device__ __forceinline__ unsigned int mapa_u32(unsigned int a, unsigned int rank) {
    unsigned int r;
    asm("mapa.shared::cluster.u32 %0, %1, %2;" : "=r"(r) : "r"(a), "r"(rank));
    return r;
}
__device__ __forceinline__ void stc_f32(unsigned int a, float v) {
    asm volatile("st.shared::cluster.f32 [%0], %1;" :: "r"(a), "f"(v) : "memory");
}
__device__ __forceinline__ void stc_rel_i32(unsigned int a, int v) {
    asm volatile("st.release.cluster.shared::cluster.b32 [%0], %1;"
                 :: "r"(a), "r"(v) : "memory");
}
__device__ __forceinline__ int ld_acq_i32(unsigned int a) {
    int v;
    asm volatile("ld.acquire.cluster.shared::cta.b32 %0, [%1];"
                 : "=r"(v) : "r"(a) : "memory");
    return v;
}
__device__ __forceinline__ void poll_ge(unsigned int a, int tgt) {
    while (ld_acq_i32(a) < tgt) {}
}

__global__ void __launch_bounds__(256) convert_weights_kernel(
    const float* __restrict__ W1, const float* __restrict__ Whh,
    const float* __restrict__ Wih)
{
    int i = blockIdx.x * 256 + threadIdx.x;
    if (i < D_ * E_) {
        int d = i >> 8, c = i & 255;
        g_whc[i] = __floats2half2_rn(W1[d * E_ + c], W1[(D_ + d) * E_ + c]);
    }
    if (i < D_ * 4 * D_) g_whh[i] = __float2half_rn(Whh[i]);
    if (i < O_ * 4 * D_) g_wih[i] = __float2half_rn(Wih[i]);
}

__global__ void __launch_bounds__(NT, 1) __cluster_dims__(2, 1, 1)
attn_decoder_kernel(
    const float* __restrict__ x, const float* __restrict__ yh,
    const float* __restrict__ h0, const float* __restrict__ c0,
    const float* __restrict__ W1, const float* __restrict__ b1,
    const float* __restrict__ w2, const float* __restrict__ b2,
    const float* __restrict__ bih, const float* __restrict__ bhh,
    const float* __restrict__ fcW, const float* __restrict__ fcb)
{
    extern __shared__ char smraw[];
    __half* ep_sm = (__half*)(smraw + OFF_EP);
    float*  XF    = (float*)(smraw + OFF_XF);
    float*  YF    = (float*)(smraw + OFF_YF);
    float*  pwhc  = (float*)(smraw + OFF_PWHC);   // [16ks][2bt][128]
    float*  pwhh  = (float*)(smraw + OFF_PWHH);   // [4kg][2bt][512]
    float*  gfin  = (float*)(smraw + OFF_GFIN);   // [2bt][512]
    float*  partA = (float*)(smraw + OFF_PA);
    float*  hsm   = (float*)(smraw + OFF_H);      // [2][256]
    float*  csm   = (float*)(smraw + OFF_C);
    float*  hcf   = (float*)(smraw + OFF_HCF);    // [256] own batch
    float*  sc    = (float*)(smraw + OFF_SC);
    float*  ytl2  = (float*)(smraw + OFF_YT);     // [2][64]
    float*  w2s   = (float*)(smraw + OFF_W2);
    int*    flg   = (int*)(smraw + OFF_FLG);

    const int myb  = blockIdx.x;
    const int rho  = myb & 1;
    const int pb   = myb & ~1;
    const int t    = threadIdx.x;
    const int lane = t & 31, w = t >> 5;
    const unsigned int base = smem_u32(smraw);
    const unsigned int peer = mapa_u32(base, 1 - rho);
    const unsigned int fl_hc_loc  = base + OFF_FLG + FL_HC;
    const unsigned int fl_ytl_loc = base + OFF_FLG + FL_YTL;
    const unsigned int fl_st_loc  = base + OFF_FLG + FL_ST;
    const unsigned int fl_hc_pr   = peer + OFF_FLG + FL_HC;
    const unsigned int fl_ytl_pr  = peer + OFF_FLG + FL_YTL;
    const unsigned int fl_st_pr   = peer + OFF_FLG + FL_ST;

    // ================= prologue =================
    if (t < 12) flg[t] = 0;
    __half* x16 = (__half*)(smraw + OFF_EP);   // x16 lives where ep will live
    {
        const float* xb = x + (size_t)myb * S_ * E_;
        for (int i = t; i < S_ * E_; i += NT) x16[i] = __float2half_rn(xb[i]);
    }
    for (int i = t; i < 512; i += NT) {
        int bt = i >> 8, d = i & 255;
        hsm[i] = h0[(pb + bt) * D_ + d];
        csm[i] = c0[(pb + bt) * D_ + d];
    }
    if (t < 256) w2s[t] = w2[t];
    const float b2c = b2[0];
    __syncthreads();

    const int rP = t >> 6, jP = t & 63;
    // XF[s][j] = sum_e x[s][e]*fcW[e][j]
    {
        float acc[16];
        #pragma unroll
        for (int si = 0; si < 16; si++) acc[si] = 0.f;
        for (int e = 0; e < E_; e++) {
            float wv = fcW[e * 64 + jP];
            #pragma unroll
            for (int si = 0; si < 16; si++)
                acc[si] = fmaf(__half2float(x16[(16 * rP + si) * E_ + e]), wv, acc[si]);
        }
        #pragma unroll
        for (int si = 0; si < 16; si++) XF[(16 * rP + si) * 64 + jP] = acc[si];
    }
    // YF[t][j] = fcb[j] + sum_o yh[myb][t][o]*fcW[256+o][j]
    {
        float acc[16];
        #pragma unroll
        for (int si = 0; si < 16; si++) acc[si] = 0.f;
        const float* yhb = yh + (size_t)myb * S_ * O_;
        for (int o = 0; o < O_; o++) {
            float wv = fcW[(E_ + o) * 64 + jP];
            #pragma unroll
            for (int si = 0; si < 16; si++)
                acc[si] = fmaf(yhb[(16 * rP + si) * O_ + o], wv, acc[si]);
        }
        float fb = fcb[jP];
        #pragma unroll
        for (int si = 0; si < 16; si++) YF[(16 * rP + si) * 64 + jP] = acc[si] + fb;
    }
    // ep = x @ We, accumulated in registers, then overwrite x16 region
    {
        const float4* We4 = (const float4*)(W1 + 2 * D_ * E_);
        float4 acc[16];
        #pragma unroll
        for (int si = 0; si < 16; si++) acc[si] = make_float4(0.f, 0.f, 0.f, 0.f);
        for (int e = 0; e < E_; e++) {
            float4 wv = We4[e * 64 + jP];
            #pragma unroll
            for (int si = 0; si < 16; si++) {
                float xv = __half2float(x16[(16 * rP + si) * E_ + e]);
                acc[si].x = fmaf(xv, wv.x, acc[si].x);
                acc[si].y = fmaf(xv, wv.y, acc[si].y);
                acc[si].z = fmaf(xv, wv.z, acc[si].z);
                acc[si].w = fmaf(xv, wv.w, acc[si].w);
            }
        }
        __syncthreads();   // all x16 reads complete
        #pragma unroll
        for (int si = 0; si < 16; si++) {
            __half2* rowp = (__half2*)(ep_sm + (size_t)(16 * rP + si) * E_);
            rowp[2 * jP]     = __floats2half2_rn(acc[si].x, acc[si].y);
            rowp[2 * jP + 1] = __floats2half2_rn(acc[si].z, acc[si].w);
        }
    }
    __syncthreads();
    cluster_sync();   // flags + state initialized in both CTAs

    const uint4* whc4 = (const uint4*)g_whc;   // row d: 64 uint4
    const uint4* whh4 = (const uint4*)g_whh;   // row k: 128 uint4
    const unsigned int* wihu = (const unsigned int*)g_wih;   // row k: 512 half2

    // per-thread constants for group A
    float rb1 = 0.f, gbq[4] = {0.f, 0.f, 0.f, 0.f}, w2r[8];
    if (t < 256) {
        rb1 = b1[128 * rho + (t & 127)];
        #pragma unroll
        for (int q = 0; q < 4; q++) {
            int d = q * 256 + 128 * rho + (t & 127);
            gbq[q] = bih[d] + bhh[d];
        }
        *(float4*)&w2r[0] = *(float4*)(w2s + 8 * lane);
        *(float4*)&w2r[4] = *(float4*)(w2s + 8 * lane + 4);
    }

    const int ksW = t >> 5, cuW = t & 31;   // whc mapping (all 512)

    for (int step = 0; step < S_; step++) {
        __syncthreads();                // join A (post-pointwise) and B (post-gates)
        poll_ge(fl_st_loc, step);       // peer state landed

        // ===== whc: all 512 threads; rows 16ks..+16, own-half cols =====
        {
            const int d0 = 16 * ksW;
            ull A0[4], A1[4];
            const ull z = pack2(0.f, 0.f);
            #pragma unroll
            for (int i = 0; i < 4; i++) { A0[i] = z; A1[i] = z; }
            #pragma unroll
            for (int kk = 0; kk < 16; kk += 8) {
                uint4 v[8];
                #pragma unroll
                for (int q = 0; q < 8; q++)
                    v[q] = whc4[(d0 + kk + q) * 64 + 32 * rho + cuW];
                #pragma unroll
                for (int q = 0; q < 8; q++) {
                    int d = d0 + kk + q;
                    ull hc0 = pack2(hsm[d], csm[d]);
                    ull hc1 = pack2(hsm[256 + d], csm[256 + d]);
                    #pragma unroll
                    for (int k = 0; k < 4; k++) {
                        ull wp = h2_to_ull(((const __half2*)&v[q])[k]);
                        A0[k] = fma2(hc0, wp, A0[k]);
                        A1[k] = fma2(hc1, wp, A1[k]);
                    }
                }
            }
            float a0[4], a1[4];
            #pragma unroll
            for (int k = 0; k < 4; k++) {
                float2 f0 = unpack2(A0[k]);
                float2 f1 = unpack2(A1[k]);
                a0[k] = f0.x + f0.y;
                a1[k] = f1.x + f1.y;
            }
            ((float4*)(pwhc + (ksW * 2 + 0) * 128))[cuW] = make_float4(a0[0], a0[1], a0[2], a0[3]);
            ((float4*)(pwhc + (ksW * 2 + 1) * 128))[cuW] = make_float4(a1[0], a1[1], a1[2], a1[3]);
        }
        __syncthreads();   // pwhc ready

        if (t < 256) {
            // =================== GROUP A ===================
            {   // reduce + route hc pieces
                const int bt = t >> 7, cl = t & 127;
                float v = rb1;
                #pragma unroll
                for (int ks = 0; ks < 16; ks++) v += pwhc[(ks * 2 + bt) * 128 + cl];
                if (bt == rho) hcf[128 * rho + cl] = v;
                else stc_f32(peer + OFF_HCF + 4 * (128 * rho + cl), v);
            }
            barA();
            if (t == 0) stc_rel_i32(fl_hc_pr, step + 1);
            poll_ge(fl_hc_loc, step + 1);

            // scores: warp w -> s = 16w..16w+15 (ep in SMEM)
            {
                float hcr[8];
                *(float4*)&hcr[0] = *(float4*)(hcf + 8 * lane);
                *(float4*)&hcr[4] = *(float4*)(hcf + 8 * lane + 4);
                #pragma unroll 2
                for (int si = 0; si < 16; si++) {
                    int s = 16 * w + si;
                    uint4 u = ((const uint4*)ep_sm)[(s << 5) + lane];
                    float sum = 0.f;
                    #pragma unroll
                    for (int k = 0; k < 4; k++) {
                        float2 p = __half22float2(((const __half2*)&u)[k]);
                        sum = fmaf(tanh_a(p.x + hcr[2 * k]),     w2r[2 * k],     sum);
                        sum = fmaf(tanh_a(p.y + hcr[2 * k + 1]), w2r[2 * k + 1], sum);
                    }
                    #pragma unroll
                    for (int off = 16; off; off >>= 1)
                        sum += __shfl_xor_sync(0xffffffffu, sum, off);
                    if (lane == 0) sc[s] = sum + b2c;
                }
            }
            barA();
            if (w == 0) {   // softmax
                float v0 = sc[lane], v1 = sc[32 + lane], v2 = sc[64 + lane], v3 = sc[96 + lane];
                float m = fmaxf(fmaxf(v0, v1), fmaxf(v2, v3));
                #pragma unroll
                for (int off = 16; off; off >>= 1)
                    m = fmaxf(m, __shfl_xor_sync(0xffffffffu, m, off));
                float e0 = __expf(v0 - m), e1 = __expf(v1 - m);
                float e2 = __expf(v2 - m), e3 = __expf(v3 - m);
                float s2 = e0 + e1 + e2 + e3;
                #pragma unroll
                for (int off = 16; off; off >>= 1)
                    s2 += __shfl_xor_sync(0xffffffffu, s2, off);
                float inv = __fdividef(1.f, s2);
                sc[lane]      = e0 * inv;
                sc[32 + lane] = e1 * inv;
                sc[64 + lane] = e2 * inv;
                sc[96 + lane] = e3 * inv;
            }
            barA();
            {   // ytl partials
                const int sq = t >> 6, j = t & 63;
                float acc = 0.f;
                #pragma unroll 8
                for (int s = 32 * sq; s < 32 * sq + 32; s++)
                    acc = fmaf(sc[s], XF[s * 64 + j], acc);
                partA[t] = acc;
            }
            barA();
            if (t < O_) {
                float v = YF[step * 64 + t] + partA[t] + partA[64 + t]
                        + partA[128 + t] + partA[192 + t];
                ytl2[rho * 64 + t] = v;
                stc_f32(peer + OFF_YT + 4 * (rho * 64 + t), v);
            }
            barA();
            if (t == 0) stc_rel_i32(fl_ytl_pr, step + 1);
            barrive(6);

            bsync(4);   // gates assembled by B
            {   // pointwise: own-half cols, both batches; export halves
                const int bt = t >> 7, dl = t & 127;
                const int d = 128 * rho + dl;
                const float* g = gfin + bt * 512;
                float gi = g[dl]       + gbq[0];
                float gf = g[128 + dl] + gbq[1];
                float gg = g[256 + dl] + gbq[2];
                float go = g[384 + dl] + gbq[3];
                float cv = csm[bt * 256 + d];
                float cn = fmaf(sigm_f(gf), cv, sigm_f(gi) * tanh_f(gg));
                float hn = sigm_f(go) * tanh_f(cn);
                hsm[bt * 256 + d] = hn;
                csm[bt * 256 + d] = cn;
                stc_f32(peer + OFF_H + 4 * (bt * 256 + d), hn);
                stc_f32(peer + OFF_C + 4 * (bt * 256 + d), cn);
            }
            barA();
            if (t == 0) stc_rel_i32(fl_st_pr, step + 1);
        } else {
            // =================== GROUP B ===================
            const int tb = t - 256;
            const int kg = tb >> 6, cu2 = tb & 63;
            const int qg = cu2 >> 4, c16 = cu2 & 15;
            const int colu = qg * 32 + 16 * rho + c16;
            const int qa = tb >> 6, pa = tb & 63;
            const int cidx = qa * 128 + 64 * rho + pa;

            // ---- Whh: own-half cols, 64 rows per thread, both batches ----
            {
                ull A0[4], A1[4];
                const ull z = pack2(0.f, 0.f);
                #pragma unroll
                for (int i = 0; i < 4; i++) { A0[i] = z; A1[i] = z; }
                const int k0b = 64 * kg;
                #pragma unroll 2
                for (int k0 = 0; k0 < 64; k0 += 8) {
                    uint4 v[8];
                    #pragma unroll
                    for (int q = 0; q < 8; q++)
                        v[q] = whh4[(k0b + k0 + q) * 128 + colu];
                    #pragma unroll
                    for (int q = 0; q < 8; q++) {
                        float h0v = hsm[k0b + k0 + q];
                        float h1v = hsm[256 + k0b + k0 + q];
                        ull hh0 = pack2(h0v, h0v);
                        ull hh1 = pack2(h1v, h1v);
                        #pragma unroll
                        for (int k = 0; k < 4; k++) {
                            ull wp = h2_to_ull(((const __half2*)&v[q])[k]);
                            A0[k] = fma2(hh0, wp, A0[k]);
                            A1[k] = fma2(hh1, wp, A1[k]);
                        }
                    }
                }
                float* d0p = pwhh + (kg * 2 + 0) * 512 + qg * 128 + c16 * 8;
                float* d1p = pwhh + (kg * 2 + 1) * 512 + qg * 128 + c16 * 8;
                float2 f;
                f = unpack2(A0[0]); ((float2*)d0p)[0] = f;
                f = unpack2(A0[1]); ((float2*)d0p)[1] = f;
                f = unpack2(A0[2]); ((float2*)d0p)[2] = f;
                f = unpack2(A0[3]); ((float2*)d0p)[3] = f;
                f = unpack2(A1[0]); ((float2*)d1p)[0] = f;
                f = unpack2(A1[1]); ((float2*)d1p)[1] = f;
                f = unpack2(A1[2]); ((float2*)d1p)[2] = f;
                f = unpack2(A1[3]); ((float2*)d1p)[3] = f;
            }
            barB();                          // pwhh complete
            bsync(6);                        // own ytl ready (A)
            poll_ge(fl_ytl_loc, step + 1);   // peer ytl landed

            // ---- wih + gate assembly ----
            {
                ull C0 = pack2(0.f, 0.f), C1 = pack2(0.f, 0.f);
                #pragma unroll 2
                for (int k0 = 0; k0 < 64; k0 += 8) {
                    unsigned int u[8];
                    #pragma unroll
                    for (int q = 0; q < 8; q++) u[q] = wihu[(k0 + q) * 512 + cidx];
                    #pragma unroll
                    for (int q = 0; q < 8; q++) {
                        float y0 = ytl2[k0 + q], y1 = ytl2[64 + k0 + q];
                        ull wp = h2_to_ull(*(__half2*)&u[q]);
                        C0 = fma2(pack2(y0, y0), wp, C0);
                        C1 = fma2(pack2(y1, y1), wp, C1);
                    }
                }
                float2 acc0 = unpack2(C0), acc1 = unpack2(C1);
                const int hc512 = qa * 128 + 2 * pa;
                #pragma unroll
                for (int k2 = 0; k2 < 4; k2++) {
                    acc0.x += pwhh[(k2 * 2 + 0) * 512 + hc512];
                    acc0.y += pwhh[(k2 * 2 + 0) * 512 + hc512 + 1];
                    acc1.x += pwhh[(k2 * 2 + 1) * 512 + hc512];
                    acc1.y += pwhh[(k2 * 2 + 1) * 512 + hc512 + 1];
                }
                *(float2*)(gfin + hc512)       = acc0;
                *(float2*)(gfin + 512 + hc512) = acc1;
            }
            barrive(4);   // gates published to A
        }
    }

    // ================= epilogue =================
    if (t < 256) {
        poll_ge(fl_st_loc, S_);
        float acc = 0.f;
        const float* xg = x + (size_t)myb * S_ * E_;
        #pragma unroll 4
        for (int s = 0; s < S_; s++)
            acc = fmaf(sc[s], xg[s * E_ + t], acc);
        g_hctx[myb * 512 + t]       = hsm[rho * 256 + t];
        g_hctx[myb * 512 + 256 + t] = acc;
    }
    cluster_sync();
}

// out[128, 8192] = g_hctx[128,512] @ fc_out_W[512,8192] + b
__global__ void __launch_bounds__(256, 1) fcout_kernel(
    const float* __restrict__ W, const float* __restrict__ bias,
    float* __restrict__ out)
{
    __shared__ float As[32][128];
    __shared__ float Ws[32][64];
    const int n0 = blockIdx.x * 64;
    const int t  = threadIdx.x;
    const int tx = t & 7, ty = t >> 3;

    float bv[8];
    #pragma unroll
    for (int jj = 0; jj < 8; jj++) bv[jj] = bias[n0 + 8 * tx + jj];

    float acc[4][8];
    #pragma unroll
    for (int i = 0; i < 4; i++)
        #pragma unroll
        for (int jj = 0; jj < 8; jj++) acc[i][jj] = 0.f;

    for (int k0 = 0; k0 < 512; k0 += 32) {
        {
            int q    = t & 7;
            int row0 = t >> 3;
            #pragma unroll
            for (int i = 0; i < 4; i++) {
                int rr = row0 + 32 * i;
                float4 v = *(const float4*)(g_hctx + rr * 512 + k0 + 4 * q);
                As[4 * q + 0][rr] = v.x;
                As[4 * q + 1][rr] = v.y;
                As[4 * q + 2][rr] = v.z;
                As[4 * q + 3][rr] = v.w;
            }
            int nq  = t & 15;
            int kk0 = t >> 4;
            #pragma unroll
            for (int i = 0; i < 2; i++) {
                int kk = kk0 + 16 * i;
                float4 v = *(const float4*)(W + (size_t)(k0 + kk) * 8192 + n0 + 4 * nq);
                *(float4*)(&Ws[kk][4 * nq]) = v;
            }
        }
        __syncthreads();
        #pragma unroll 8
        for (int kk = 0; kk < 32; kk++) {
            float a[4], wv[8];
            #pragma unroll
            for (int i = 0; i < 4; i++) a[i] = As[kk][4 * ty + i];
            #pragma unroll
            for (int jj = 0; jj < 8; jj++) wv[jj] = Ws[kk][8 * tx + jj];
            #pragma unroll
            for (int i = 0; i < 4; i++)
                #pragma unroll
                for (int jj = 0; jj < 8; jj++)
                    acc[i][jj] = fmaf(a[i], wv[jj], acc[i][jj]);
        }
        __syncthreads();
    }
    #pragma unroll
    for (int i = 0; i < 4; i++) {
        int bb = 4 * ty + i;
        #pragma unroll
        for (int jj = 0; jj < 8; jj++)
            out[(size_t)bb * 8192 + n0 + 8 * tx + jj] = acc[i][jj] + bv[jj];
    }
}

extern "C" void kernel_launch(void* const* d_in, const int* in_sizes, int n_in,
                              void* d_out, int out_size)
{
    const float* x   = (const float*)d_in[0];
    const float* yh  = (const float*)d_in[1];
    const float* h0  = (const float*)d_in[2];
    const float* c0  = (const float*)d_in[3];
    const float* W1  = (const float*)d_in[4];
    const float* b1  = (const float*)d_in[5];
    const float* w2  = (const float*)d_in[6];
    const float* b2  = (const float*)d_in[7];
    const float* Wih = (const float*)d_in[8];
    const float* Whh = (const float*)d_in[9];
    const float* bih = (const float*)d_in[10];
    const float* bhh = (const float*)d_in[11];
    const float* fcW = (const float*)d_in[12];
    const float* fcb = (const float*)d_in[13];
    const float* foW = (const float*)d_in[14];
    const float* fob = (const float*)d_in[15];

    convert_weights_kernel<<<(D_ * 4 * D_ + 255) / 256, 256>>>(W1, Whh, Wih);

    cudaFuncSetAttribute(attn_decoder_kernel,
                         cudaFuncAttributeMaxDynamicSharedMemorySize, SMEM_BYTES);
    attn_decoder_kernel<<<B_, NT, SMEM_BYTES>>>(x, yh, h0, c0, W1, b1, w2, b2,
                                                bih, bhh, fcW, fcb);
    fcout_kernel<<<128, 256>>>(foW, fob, (float*)d_out);
}

// round 16
// speedup vs baseline: 1.0318x; 1.0318x over previous
#include <cuda_runtime.h>
#include <cuda_fp16.h>
#include <cstdint>
#include <math.h>

namespace {
constexpr int B_ = 128, S_ = 128, E_ = 256, D_ = 256, O_ = 64;
constexpr int NT = 512;

// dynamic smem layout (bytes)
constexpr int OFF_EP   = 0;        // half [128][256]: x16 (prologue) then ep  65536
constexpr int OFF_XF   = 65536;    // f32 [128][64]                            32768
constexpr int OFF_YF   = 98304;    // f32 [128][64] (incl fcb)                 32768
constexpr int OFF_PWHC = 131072;   // f32 [8][2][128]                           8192
constexpr int OFF_PWHH = 139264;   // f32 [4][2][512]                          16384
constexpr int OFF_GFIN = 155648;   // f32 [2][512]                              4096
constexpr int OFF_PA   = 159744;   // f32 [256]                                 1024
constexpr int OFF_H    = 160768;   // f32 [2][256]
constexpr int OFF_C    = 162816;   // f32 [2][256]
constexpr int OFF_HCF  = 164864;   // f32 [256] own-batch hc
constexpr int OFF_SC   = 165888;   // f32 [128]
constexpr int OFF_YT   = 166400;   // f32 [2][64]
constexpr int OFF_W2   = 166912;   // f32 [256]
constexpr int OFF_FLG  = 167936;   // int flags
constexpr int SMEM_BYTES = 168192;
constexpr int FL_HC = 0, FL_YTL = 16, FL_ST = 32;   // byte offsets in FLG
}

typedef unsigned long long ull;

// fp16 weights (converted once per launch)
__device__ __half2 g_whc[D_ * E_];        // (Wh, Wc) interleaved [d][c]
__device__ __half  g_whh[D_ * 4 * D_];    // [256][1024]
__device__ __half  g_wih[O_ * 4 * D_];    // [64][1024]
__device__ float   g_hctx[B_ * (D_ + E_)];

__device__ __forceinline__ float sigm_f(float x) {
    float e = __expf(-x);
    return __fdividef(1.f, 1.f + e);
}
__device__ __forceinline__ float tanh_f(float x) {
    float e = __expf(2.f * x);
    return 1.f - __fdividef(2.f, e + 1.f);
}
__device__ __forceinline__ float tanh_a(float x) {
    float y;
    asm("tanh.approx.f32 %0, %1;" : "=f"(y) : "f"(x));
    return y;
}
__device__ __forceinline__ ull pack2(float lo, float hi) {
    ull r;
    asm("mov.b64 %0, {%1, %2};" : "=l"(r) : "f"(lo), "f"(hi));
    return r;
}
__device__ __forceinline__ ull fma2(ull a, ull b, ull c) {
    ull d;
    asm("fma.rn.f32x2 %0, %1, %2, %3;" : "=l"(d) : "l"(a), "l"(b), "l"(c));
    return d;
}
__device__ __forceinline__ float2 unpack2(ull v) {
    float2 f;
    asm("mov.b64 {%0, %1}, %2;" : "=f"(f.x), "=f"(f.y) : "l"(v));
    return f;
}
__device__ __forceinline__ ull h2_to_ull(__half2 h) {
    float2 p = __half22float2(h);
    return pack2(p.x, p.y);
}
__device__ __forceinline__ void barA() { asm volatile("bar.sync 1, 256;" ::: "memory"); }
__device__ __forceinline__ void barB() { asm volatile("bar.sync 2, 256;" ::: "memory"); }
__device__ __forceinline__ void bsync(int id) {
    asm volatile("bar.sync %0, 512;" :: "r"(id) : "memory");
}
__device__ __forceinline__ void barrive(int id) {
    asm volatile("bar.arrive %0, 512;" :: "r"(id) : "memory");
}
__device__ __forceinline__ void cluster_sync() {
    asm volatile("barrier.cluster.arrive.aligned;" ::: "memory");
    asm volatile("barrier.cluster.wait.aligned;" ::: "memory");
}
__device__ __forceinline__ unsigned int smem_u32(const void* p) {
    unsigned int a;
    asm("{ .reg .u64 t; cvta.to.shared.u64 t, %1; cvt.u32.u64 %0, t; }" : "=r"(a) : "l"(p));
    return a;
}
__device__ __forceinline__ unsigned int mapa_u32(unsigned int a, unsigned int rank) {
    unsigned int r;
    asm("mapa.shared::cluster.u32 %0, %1, %2;" : "=r"(r) : "r"(a), "r"(rank));
    return r;
}
__device__ __forceinline__ void stc_f32(unsigned int a, float v) {
    asm volatile("st.shared::cluster.f32 [%0], %1;" :: "r"(a), "f"(v) : "memory");
}
__device__ __forceinline__ void stc_rel_i32(unsigned int a, int v) {
    asm volatile("st.release.cluster.shared::cluster.b32 [%0], %1;"
                 :: "r"(a), "r"(v) : "memory");
}
__device__ __forceinline__ int ld_acq_i32(unsigned int a) {
    int v;
    asm volatile("ld.acquire.cluster.shared::cta.b32 %0, [%1];"
                 : "=r"(v) : "r"(a) : "memory");
    return v;
}
__device__ __forceinline__ void poll_ge(unsigned int a, int tgt) {
    while (ld_acq_i32(a) < tgt) {}
}

__global__ void __launch_bounds__(256) convert_weights_kernel(
    const float* __restrict__ W1, const float* __restrict__ Whh,
    const float* __restrict__ Wih)
{
    int i = blockIdx.x * 256 + threadIdx.x;
    if (i < D_ * E_) {
        int d = i >> 8, c = i & 255;
        g_whc[i] = __floats2half2_rn(W1[d * E_ + c], W1[(D_ + d) * E_ + c]);
    }
    if (i < D_ * 4 * D_) g_whh[i] = __float2half_rn(Whh[i]);
    if (i < O_ * 4 * D_) g_wih[i] = __float2half_rn(Wih[i]);
}

__global__ void __launch_bounds__(NT, 1) __cluster_dims__(2, 1, 1)
attn_decoder_kernel(
    const float* __restrict__ x, const float* __restrict__ yh,
    const float* __restrict__ h0, const float* __restrict__ c0,
    const float* __restrict__ W1, const float* __restrict__ b1,
    const float* __restrict__ w2, const float* __restrict__ b2,
    const float* __restrict__ bih, const float* __restrict__ bhh,
    const float* __restrict__ fcW, const float* __restrict__ fcb)
{
    extern __shared__ char smraw[];
    __half* ep_sm = (__half*)(smraw + OFF_EP);
    float*  XF    = (float*)(smraw + OFF_XF);
    float*  YF    = (float*)(smraw + OFF_YF);
    float*  pwhc  = (float*)(smraw + OFF_PWHC);   // [8ks][2bt][128]
    float*  pwhh  = (float*)(smraw + OFF_PWHH);   // [4kg][2bt][512]
    float*  gfin  = (float*)(smraw + OFF_GFIN);   // [2bt][512]
    float*  partA = (float*)(smraw + OFF_PA);
    float*  hsm   = (float*)(smraw + OFF_H);      // [2][256]
    float*  csm   = (float*)(smraw + OFF_C);
    float*  hcf   = (float*)(smraw + OFF_HCF);    // [256] own batch
    float*  sc    = (float*)(smraw + OFF_SC);
    float*  ytl2  = (float*)(smraw + OFF_YT);     // [2][64]
    float*  w2s   = (float*)(smraw + OFF_W2);
    int*    flg   = (int*)(smraw + OFF_FLG);

    const int myb  = blockIdx.x;
    const int rho  = myb & 1;
    const int pb   = myb & ~1;
    const int t    = threadIdx.x;
    const int lane = t & 31, w = t >> 5;
    const unsigned int base = smem_u32(smraw);
    const unsigned int peer = mapa_u32(base, 1 - rho);
    const unsigned int fl_hc_loc  = base + OFF_FLG + FL_HC;
    const unsigned int fl_ytl_loc = base + OFF_FLG + FL_YTL;
    const unsigned int fl_st_loc  = base + OFF_FLG + FL_ST;
    const unsigned int fl_hc_pr   = peer + OFF_FLG + FL_HC;
    const unsigned int fl_ytl_pr  = peer + OFF_FLG + FL_YTL;
    const unsigned int fl_st_pr   = peer + OFF_FLG + FL_ST;

    // ================= prologue (fused: x16 -> XF/YF/ep in-place) =================
    if (t < 12) flg[t] = 0;
    __half* x16 = (__half*)(smraw + OFF_EP);   // x16 lives where ep will live
    {
        const float* xb = x + (size_t)myb * S_ * E_;
        for (int i = t; i < S_ * E_; i += NT) x16[i] = __float2half_rn(xb[i]);
    }
    for (int i = t; i < 512; i += NT) {
        int bt = i >> 8, d = i & 255;
        hsm[i] = h0[(pb + bt) * D_ + d];
        csm[i] = c0[(pb + bt) * D_ + d];
    }
    if (t < 256) w2s[t] = w2[t];
    const float b2c = b2[0];
    __syncthreads();

    const int rP = t >> 6, jP = t & 63;
    // XF[s][j] = sum_e x[s][e]*fcW[e][j]
    {
        float acc[16];
        #pragma unroll
        for (int si = 0; si < 16; si++) acc[si] = 0.f;
        for (int e = 0; e < E_; e++) {
            float wv = fcW[e * 64 + jP];
            #pragma unroll
            for (int si = 0; si < 16; si++)
                acc[si] = fmaf(__half2float(x16[(16 * rP + si) * E_ + e]), wv, acc[si]);
        }
        #pragma unroll
        for (int si = 0; si < 16; si++) XF[(16 * rP + si) * 64 + jP] = acc[si];
    }
    // YF[t][j] = fcb[j] + sum_o yh[myb][t][o]*fcW[256+o][j]
    {
        float acc[16];
        #pragma unroll
        for (int si = 0; si < 16; si++) acc[si] = 0.f;
        const float* yhb = yh + (size_t)myb * S_ * O_;
        for (int o = 0; o < O_; o++) {
            float wv = fcW[(E_ + o) * 64 + jP];
            #pragma unroll
            for (int si = 0; si < 16; si++)
                acc[si] = fmaf(yhb[(16 * rP + si) * O_ + o], wv, acc[si]);
        }
        float fb = fcb[jP];
        #pragma unroll
        for (int si = 0; si < 16; si++) YF[(16 * rP + si) * 64 + jP] = acc[si] + fb;
    }
    // ep = x @ We, register-accumulated, then overwrite the x16 region (fp16)
    {
        const float4* We4 = (const float4*)(W1 + 2 * D_ * E_);
        float4 acc[16];
        #pragma unroll
        for (int si = 0; si < 16; si++) acc[si] = make_float4(0.f, 0.f, 0.f, 0.f);
        for (int e = 0; e < E_; e++) {
            float4 wv = We4[e * 64 + jP];
            #pragma unroll
            for (int si = 0; si < 16; si++) {
                float xv = __half2float(x16[(16 * rP + si) * E_ + e]);
                acc[si].x = fmaf(xv, wv.x, acc[si].x);
                acc[si].y = fmaf(xv, wv.y, acc[si].y);
                acc[si].z = fmaf(xv, wv.z, acc[si].z);
                acc[si].w = fmaf(xv, wv.w, acc[si].w);
            }
        }
        __syncthreads();   // all x16 reads complete before overwrite
        #pragma unroll
        for (int si = 0; si < 16; si++) {
            __half2* rowp = (__half2*)(ep_sm + (size_t)(16 * rP + si) * E_);
            rowp[2 * jP]     = __floats2half2_rn(acc[si].x, acc[si].y);
            rowp[2 * jP + 1] = __floats2half2_rn(acc[si].z, acc[si].w);
        }
    }
    __syncthreads();
    cluster_sync();   // flags + state initialized in both CTAs

    const uint4* whc4 = (const uint4*)g_whc;   // row d: 64 uint4
    const uint4* whh4 = (const uint4*)g_whh;   // row k: 128 uint4
    const unsigned int* wihu = (const unsigned int*)g_wih;   // row k: 512 half2

    if (t < 256) {
        // =================== GROUP A ===================
        float rb1 = b1[128 * rho + (t & 127)];
        float gbq[4];
        #pragma unroll
        for (int q = 0; q < 4; q++) {
            int d = q * 256 + 128 * rho + (t & 127);
            gbq[q] = bih[d] + bhh[d];
        }
        float w2r[8];
        *(float4*)&w2r[0] = *(float4*)(w2s + 8 * lane);
        *(float4*)&w2r[4] = *(float4*)(w2s + 8 * lane + 4);

        barrive(5);   // state staged for B's step 0
        for (int step = 0; step < S_; step++) {
            bsync(3);   // whc partials ready (B)
            {   // reduce + route hc pieces
                const int bt = t >> 7, cl = t & 127;
                float v = rb1;
                #pragma unroll
                for (int ks = 0; ks < 8; ks++) v += pwhc[(ks * 2 + bt) * 128 + cl];
                if (bt == rho) hcf[128 * rho + cl] = v;
                else stc_f32(peer + OFF_HCF + 4 * (128 * rho + cl), v);
            }
            barA();
            if (t == 0) stc_rel_i32(fl_hc_pr, step + 1);
            poll_ge(fl_hc_loc, step + 1);

            // scores: warp w -> s = 16w..16w+15 (ep in SMEM)
            {
                float hcr[8];
                *(float4*)&hcr[0] = *(float4*)(hcf + 8 * lane);
                *(float4*)&hcr[4] = *(float4*)(hcf + 8 * lane + 4);
                #pragma unroll 2
                for (int si = 0; si < 16; si++) {
                    int s = 16 * w + si;
                    uint4 u = ((const uint4*)ep_sm)[(s << 5) + lane];
                    float sum = 0.f;
                    #pragma unroll
                    for (int k = 0; k < 4; k++) {
                        float2 p = __half22float2(((const __half2*)&u)[k]);
                        sum = fmaf(tanh_a(p.x + hcr[2 * k]),     w2r[2 * k],     sum);
                        sum = fmaf(tanh_a(p.y + hcr[2 * k + 1]), w2r[2 * k + 1], sum);
                    }
                    #pragma unroll
                    for (int off = 16; off; off >>= 1)
                        sum += __shfl_xor_sync(0xffffffffu, sum, off);
                    if (lane == 0) sc[s] = sum + b2c;
                }
            }
            barA();
            if (w == 0) {   // softmax
                float v0 = sc[lane], v1 = sc[32 + lane], v2 = sc[64 + lane], v3 = sc[96 + lane];
                float m = fmaxf(fmaxf(v0, v1), fmaxf(v2, v3));
                #pragma unroll
                for (int off = 16; off; off >>= 1)
                    m = fmaxf(m, __shfl_xor_sync(0xffffffffu, m, off));
                float e0 = __expf(v0 - m), e1 = __expf(v1 - m);
                float e2 = __expf(v2 - m), e3 = __expf(v3 - m);
                float s2 = e0 + e1 + e2 + e3;
                #pragma unroll
                for (int off = 16; off; off >>= 1)
                    s2 += __shfl_xor_sync(0xffffffffu, s2, off);
                float inv = __fdividef(1.f, s2);
                sc[lane]      = e0 * inv;
                sc[32 + lane] = e1 * inv;
                sc[64 + lane] = e2 * inv;
                sc[96 + lane] = e3 * inv;
            }
            barA();
            {   // ytl partials
                const int sq = t >> 6, j = t & 63;
                float acc = 0.f;
                #pragma unroll 8
                for (int s = 32 * sq; s < 32 * sq + 32; s++)
                    acc = fmaf(sc[s], XF[s * 64 + j], acc);
                partA[t] = acc;
            }
            barA();
            if (t < O_) {
                float v = YF[step * 64 + t] + partA[t] + partA[64 + t]
                        + partA[128 + t] + partA[192 + t];
                ytl2[rho * 64 + t] = v;
                stc_f32(peer + OFF_YT + 4 * (rho * 64 + t), v);
            }
            barA();
            if (t == 0) stc_rel_i32(fl_ytl_pr, step + 1);
            barrive(6);

            bsync(4);   // gates assembled by B
            {   // pointwise: own-half cols, both batches; export halves
                const int bt = t >> 7, dl = t & 127;
                const int d = 128 * rho + dl;
                const float* g = gfin + bt * 512;
                float gi = g[dl]       + gbq[0];
                float gf = g[128 + dl] + gbq[1];
                float gg = g[256 + dl] + gbq[2];
                float go = g[384 + dl] + gbq[3];
                float cv = csm[bt * 256 + d];
                float cn = fmaf(sigm_f(gf), cv, sigm_f(gi) * tanh_f(gg));
                float hn = sigm_f(go) * tanh_f(cn);
                hsm[bt * 256 + d] = hn;
                csm[bt * 256 + d] = cn;
                stc_f32(peer + OFF_H + 4 * (bt * 256 + d), hn);
                stc_f32(peer + OFF_C + 4 * (bt * 256 + d), cn);
            }
            barA();
            if (t == 0) stc_rel_i32(fl_st_pr, step + 1);
            barrive(5);
        }

        // epilogue
        poll_ge(fl_st_loc, S_);
        {
            float acc = 0.f;
            const float* xg = x + (size_t)myb * S_ * E_;
            #pragma unroll 4
            for (int s = 0; s < S_; s++)
                acc = fmaf(sc[s], xg[s * E_ + t], acc);
            g_hctx[myb * 512 + t]       = hsm[rho * 256 + t];
            g_hctx[myb * 512 + 256 + t] = acc;
        }
    } else {
        // =================== GROUP B: weight streamer ===================
        const int tb = t - 256;
        // whc mapping: 8 k-groups x 32 uint4-cols
        const int ks = tb >> 5, cu = tb & 31;
        // whh mapping: 4 k-groups x 64 col-threads
        const int kg = tb >> 6, cu2 = tb & 63;
        const int qg = cu2 >> 4, c16 = cu2 & 15;
        const int colu = qg * 32 + 16 * rho + c16;
        // wih/assemble mapping: (qa, pa)
        const int qa = tb >> 6, pa = tb & 63;
        const int cidx = qa * 128 + 64 * rho + pa;

        for (int step = 0; step < S_; step++) {
            bsync(5);                       // local halves staged by A
            poll_ge(fl_st_loc, step);       // peer halves landed

            // ---- whc: own-half cols, both batches ----
            {
                const int d0 = 32 * ks;
                ull A0[4], A1[4];
                const ull z = pack2(0.f, 0.f);
                #pragma unroll
                for (int i = 0; i < 4; i++) { A0[i] = z; A1[i] = z; }
                #pragma unroll
                for (int kk = 0; kk < 32; kk += 8) {
                    uint4 v[8];
                    #pragma unroll
                    for (int q = 0; q < 8; q++)
                        v[q] = whc4[(d0 + kk + q) * 64 + 32 * rho + cu];
                    #pragma unroll
                    for (int q = 0; q < 8; q++) {
                        int d = d0 + kk + q;
                        ull hc0 = pack2(hsm[d], csm[d]);
                        ull hc1 = pack2(hsm[256 + d], csm[256 + d]);
                        #pragma unroll
                        for (int k = 0; k < 4; k++) {
                            ull wp = h2_to_ull(((const __half2*)&v[q])[k]);
                            A0[k] = fma2(hc0, wp, A0[k]);
                            A1[k] = fma2(hc1, wp, A1[k]);
                        }
                    }
                }
                float a0[4], a1[4];
                #pragma unroll
                for (int k = 0; k < 4; k++) {
                    float2 f0 = unpack2(A0[k]);
                    float2 f1 = unpack2(A1[k]);
                    a0[k] = f0.x + f0.y;
                    a1[k] = f1.x + f1.y;
                }
                ((float4*)(pwhc + (ks * 2 + 0) * 128))[cu] = make_float4(a0[0], a0[1], a0[2], a0[3]);
                ((float4*)(pwhc + (ks * 2 + 1) * 128))[cu] = make_float4(a1[0], a1[1], a1[2], a1[3]);
            }
            barrive(3);   // hand to A

            // ---- Whh: own-half cols, 64 rows per thread, both batches ----
            {
                ull A0[4], A1[4];
                const ull z = pack2(0.f, 0.f);
                #pragma unroll
                for (int i = 0; i < 4; i++) { A0[i] = z; A1[i] = z; }
                const int k0b = 64 * kg;
                #pragma unroll 2
                for (int k0 = 0; k0 < 64; k0 += 8) {
                    uint4 v[8];
                    #pragma unroll
                    for (int q = 0; q < 8; q++)
                        v[q] = whh4[(k0b + k0 + q) * 128 + colu];
                    #pragma unroll
                    for (int q = 0; q < 8; q++) {
                        float h0v = hsm[k0b + k0 + q];
                        float h1v = hsm[256 + k0b + k0 + q];
                        ull hh0 = pack2(h0v, h0v);
                        ull hh1 = pack2(h1v, h1v);
                        #pragma unroll
                        for (int k = 0; k < 4; k++) {
                            ull wp = h2_to_ull(((const __half2*)&v[q])[k]);
                            A0[k] = fma2(hh0, wp, A0[k]);
                            A1[k] = fma2(hh1, wp, A1[k]);
                        }
                    }
                }
                float* d0p = pwhh + (kg * 2 + 0) * 512 + qg * 128 + c16 * 8;
                float* d1p = pwhh + (kg * 2 + 1) * 512 + qg * 128 + c16 * 8;
                float2 f;
                f = unpack2(A0[0]); ((float2*)d0p)[0] = f;
                f = unpack2(A0[1]); ((float2*)d0p)[1] = f;
                f = unpack2(A0[2]); ((float2*)d0p)[2] = f;
                f = unpack2(A0[3]); ((float2*)d0p)[3] = f;
                f = unpack2(A1[0]); ((float2*)d1p)[0] = f;
                f = unpack2(A1[1]); ((float2*)d1p)[1] = f;
                f = unpack2(A1[2]); ((float2*)d1p)[2] = f;
                f = unpack2(A1[3]); ((float2*)d1p)[3] = f;
            }
            barB();                          // pwhh complete
            bsync(6);                        // own ytl ready (A)
            poll_ge(fl_ytl_loc, step + 1);   // peer ytl landed

            // ---- wih + gate assembly ----
            {
                ull C0 = pack2(0.f, 0.f), C1 = pack2(0.f, 0.f);
                #pragma unroll 2
                for (int k0 = 0; k0 < 64; k0 += 8) {
                    unsigned int u[8];
                    #pragma unroll
                    for (int q = 0; q < 8; q++) u[q] = wihu[(k0 + q) * 512 + cidx];
                    #pragma unroll
                    for (int q = 0; q < 8; q++) {
                        float y0 = ytl2[k0 + q], y1 = ytl2[64 + k0 + q];
                        ull wp = h2_to_ull(*(__half2*)&u[q]);
                        C0 = fma2(pack2(y0, y0), wp, C0);
                        C1 = fma2(pack2(y1, y1), wp, C1);
                    }
                }
                float2 acc0 = unpack2(C0), acc1 = unpack2(C1);
                const int hc512 = qa * 128 + 2 * pa;
                #pragma unroll
                for (int k2 = 0; k2 < 4; k2++) {
                    acc0.x += pwhh[(k2 * 2 + 0) * 512 + hc512];
                    acc0.y += pwhh[(k2 * 2 + 0) * 512 + hc512 + 1];
                    acc1.x += pwhh[(k2 * 2 + 1) * 512 + hc512];
                    acc1.y += pwhh[(k2 * 2 + 1) * 512 + hc512 + 1];
                }
                *(float2*)(gfin + hc512)       = acc0;
                *(float2*)(gfin + 512 + hc512) = acc1;
            }
            barrive(4);   // gates published to A
        }
    }
    cluster_sync();
}

// out[128, 8192] = g_hctx[128,512] @ fc_out_W[512,8192] + b
__global__ void __launch_bounds__(256, 1) fcout_kernel(
    const float* __restrict__ W, const float* __restrict__ bias,
    float* __restrict__ out)
{
    __shared__ float As[32][128];
    __shared__ float Ws[32][64];
    const int n0 = blockIdx.x * 64;
    const int t  = threadIdx.x;
    const int tx = t & 7, ty = t >> 3;

    float bv[8];
    #pragma unroll
    for (int jj = 0; jj < 8; jj++) bv[jj] = bias[n0 + 8 * tx + jj];

    float acc[4][8];
    #pragma unroll
    for (int i = 0; i < 4; i++)
        #pragma unroll
        for (int jj = 0; jj < 8; jj++) acc[i][jj] = 0.f;

    for (int k0 = 0; k0 < 512; k0 += 32) {
        {
            int q    = t & 7;
            int row0 = t >> 3;
            #pragma unroll
            for (int i = 0; i < 4; i++) {
                int rr = row0 + 32 * i;
                float4 v = *(const float4*)(g_hctx + rr * 512 + k0 + 4 * q);
                As[4 * q + 0][rr] = v.x;
                As[4 * q + 1][rr] = v.y;
                As[4 * q + 2][rr] = v.z;
                As[4 * q + 3][rr] = v.w;
            }
            int nq  = t & 15;
            int kk0 = t >> 4;
            #pragma unroll
            for (int i = 0; i < 2; i++) {
                int kk = kk0 + 16 * i;
                float4 v = *(const float4*)(W + (size_t)(k0 + kk) * 8192 + n0 + 4 * nq);
                *(float4*)(&Ws[kk][4 * nq]) = v;
            }
        }
        __syncthreads();
        #pragma unroll 8
        for (int kk = 0; kk < 32; kk++) {
            float a[4], wv[8];
            #pragma unroll
            for (int i = 0; i < 4; i++) a[i] = As[kk][4 * ty + i];
            #pragma unroll
            for (int jj = 0; jj < 8; jj++) wv[jj] = Ws[kk][8 * tx + jj];
            #pragma unroll
            for (int i = 0; i < 4; i++)
                #pragma unroll
                for (int jj = 0; jj < 8; jj++)
                    acc[i][jj] = fmaf(a[i], wv[jj], acc[i][jj]);
        }
        __syncthreads();
    }
    #pragma unroll
    for (int i = 0; i < 4; i++) {
        int bb = 4 * ty + i;
        #pragma unroll
        for (int jj = 0; jj < 8; jj++)
            out[(size_t)bb * 8192 + n0 + 8 * tx + jj] = acc[i][jj] + bv[jj];
    }
}

extern "C" void kernel_launch(void* const* d_in, const int* in_sizes, int n_in,
                              void* d_out, int out_size)
{
    const float* x   = (const float*)d_in[0];
    const float* yh  = (const float*)d_in[1];
    const float* h0  = (const float*)d_in[2];
    const float* c0  = (const float*)d_in[3];
    const float* W1  = (const float*)d_in[4];
    const float* b1  = (const float*)d_in[5];
    const float* w2  = (const float*)d_in[6];
    const float* b2  = (const float*)d_in[7];
    const float* Wih = (const float*)d_in[8];
    const float* Whh = (const float*)d_in[9];
    const float* bih = (const float*)d_in[10];
    const float* bhh = (const float*)d_in[11];
    const float* fcW = (const float*)d_in[12];
    const float* fcb = (const float*)d_in[13];
    const float* foW = (const float*)d_in[14];
    const float* fob = (const float*)d_in[15];

    convert_weights_kernel<<<(D_ * 4 * D_ + 255) / 256, 256>>>(W1, Whh, Wih);

    cudaFuncSetAttribute(attn_decoder_kernel,
                         cudaFuncAttributeMaxDynamicSharedMemorySize, SMEM_BYTES);
    attn_decoder_kernel<<<B_, NT, SMEM_BYTES>>>(x, yh, h0, c0, W1, b1, w2, b2,
                                                bih, bhh, fcW, fcb);
    fcout_kernel<<<128, 256>>>(foW, fob, (float*)d_out);
}